// round 17
// baseline (speedup 1.0000x reference)
#include <cuda_runtime.h>
#include <cuda_bf16.h>
#include <cstdint>

// Problem constants
#define NWIN 400
#define NTOK 324
#define NPAD 336
#define CE   128
#define CC   256
#define HH   180
#define WSZ  18

// embed v2: per-(window, e-half) CTAs, 2 CTAs/SM
#define NTH_E 192
#define EBR   48
#define NBLK_E 7
#define EMB_LD 264  // words 132, mod32=4

// attn v4 (unchanged R16)
#define NTH_A 192
#define BLKR2 48
#define SCH   112
#define AVK   48
#define TH_LD 136   // words 68,  mod32=4
#define P_LD  344   // words 172, mod32=12
#define AV_LD 56    // words 28,  mod32=28
#define PJ_LD 72    // words 36,  mod32=4

#define ZONE_HALF 15232
#define OFF_P    (BLKR2 * TH_LD)
#define OFF_ZONE (OFF_P + BLKR2 * P_LD)
#define OFF_END  (OFF_ZONE + 2 * ZONE_HALF)
#define ATTN_SMEM (OFF_END * 2 + BLKR2 * 2 * 4 * 2)  // 107776 B

// ---------------- global scratch ----------------
__device__ __nv_bfloat16 g_embT [NWIN * NPAD * CC];  // [w][n][e]: e<128 theta, e>=128 phi
__device__ __nv_bfloat16 g_xw   [NWIN * CC * NPAD];  // [w][c][m]
__device__ __nv_bfloat16 g_wprojb[CC * CC];          // [o][c]

// ---------------- helpers ----------------
__device__ __forceinline__ uint32_t s2u(const __nv_bfloat16* p) {
    return (uint32_t)__cvta_generic_to_shared(p);
}
__device__ __forceinline__ void ldsm4(uint32_t& r0, uint32_t& r1, uint32_t& r2, uint32_t& r3,
                                      uint32_t a) {
    asm volatile("ldmatrix.sync.aligned.m8n8.x4.shared.b16 {%0,%1,%2,%3}, [%4];"
        : "=r"(r0), "=r"(r1), "=r"(r2), "=r"(r3) : "r"(a));
}
__device__ __forceinline__ void ldsm2(uint32_t& r0, uint32_t& r1, uint32_t a) {
    asm volatile("ldmatrix.sync.aligned.m8n8.x2.shared.b16 {%0,%1}, [%2];"
        : "=r"(r0), "=r"(r1) : "r"(a));
}
__device__ __forceinline__ void mma16816(float* c, uint32_t a0, uint32_t a1,
                                         uint32_t a2, uint32_t a3,
                                         uint32_t b0, uint32_t b1) {
    asm volatile(
        "mma.sync.aligned.m16n8k16.row.col.f32.bf16.bf16.f32 "
        "{%0,%1,%2,%3},{%4,%5,%6,%7},{%8,%9},{%0,%1,%2,%3};\n"
        : "+f"(c[0]), "+f"(c[1]), "+f"(c[2]), "+f"(c[3])
        : "r"(a0), "r"(a1), "r"(a2), "r"(a3), "r"(b0), "r"(b1));
}
__device__ __forceinline__ void st_bf2(__nv_bfloat16* p, float lo, float hi) {
    *reinterpret_cast<__nv_bfloat162*>(p) = __floats2bfloat162_rn(lo, hi);
}
__device__ __forceinline__ uint32_t pk2(float lo, float hi) {
    __nv_bfloat162 v = __floats2bfloat162_rn(lo, hi);
    return *reinterpret_cast<uint32_t*>(&v);
}
__device__ __forceinline__ void cp16(__nv_bfloat16* dst, const __nv_bfloat16* src) {
    *reinterpret_cast<uint4*>(dst) = *reinterpret_cast<const uint4*>(src);
}
__device__ __forceinline__ void cpasync16(__nv_bfloat16* smem_dst, const __nv_bfloat16* gsrc) {
    uint32_t s = (uint32_t)__cvta_generic_to_shared(smem_dst);
    asm volatile("cp.async.cg.shared.global [%0], [%1], 16;\n" :: "r"(s), "l"(gsrc));
}
#define CP_COMMIT() asm volatile("cp.async.commit_group;\n" ::: "memory")
#define CP_WAIT1()  asm volatile("cp.async.wait_group 1;\n" ::: "memory")
#define CP_WAIT0()  asm volatile("cp.async.wait_group 0;\n" ::: "memory")

// ---------------- kernel 1: embed v2 — (window, e-half) CTAs, 2 CTAs/SM ----
// smem: wcomb half [128][EMB_LD] + xb [48][EMB_LD]
#define EMBED_SMEM ((128 * EMB_LD + EBR * EMB_LD) * 2)

__global__ __launch_bounds__(NTH_E, 2) void embed_kernel(const float* __restrict__ x,
                                                         const float* __restrict__ wt,
                                                         const float* __restrict__ wp,
                                                         const float* __restrict__ wproj) {
    extern __shared__ char smem_raw[];
    __nv_bfloat16* wcomb_s = reinterpret_cast<__nv_bfloat16*>(smem_raw);  // [128][EMB_LD]
    __nv_bfloat16* xb_s = wcomb_s + 128 * EMB_LD;                         // [48][EMB_LD]

    int bid = blockIdx.x;
    int w = bid >> 1, half = bid & 1;
    int b = w / 100, rem = w % 100, wh = rem / 10, ww = rem % 10;
    int h0 = wh * WSZ, w0 = ww * WSZ;
    const float* xb = x + (size_t)b * CC * HH * HH;
    int tid = threadIdx.x;
    int warp = tid >> 5, lane = tid & 31;
    int rw = warp >> 1, cw = warp & 1;   // 3 x 2; warp covers 16 rows x 64 e-cols
    int g = lane >> 2, q = lane & 3;
    int lA = lane & 15, kA = (lane >> 4) << 3;
    int lB8 = lane & 7, sel = (lane >> 3) & 1, nh = lane >> 4;

    // bid 0 additionally converts wproj -> g_wprojb
    if (bid == 0) {
        for (int idx = tid; idx < CC * CC / 4; idx += NTH_E) {
            float4 f = *reinterpret_cast<const float4*>(&wproj[idx * 4]);
            __nv_bfloat162 lo = __floats2bfloat162_rn(f.x, f.y);
            __nv_bfloat162 hi = __floats2bfloat162_rn(f.z, f.w);
            uint2 v; v.x = *reinterpret_cast<uint32_t*>(&lo); v.y = *reinterpret_cast<uint32_t*>(&hi);
            *reinterpret_cast<uint2*>(&g_wprojb[idx * 4]) = v;
        }
    }

    // stage this half's weight rows (half 0: theta, half 1: phi)
    const float* wsrc = half ? wp : wt;
    for (int idx = tid; idx < 128 * 64; idx += NTH_E) {
        int e = idx >> 6, v = idx & 63;
        float4 f = *reinterpret_cast<const float4*>(&wsrc[e * CC + v * 4]);
        __nv_bfloat162 lo = __floats2bfloat162_rn(f.x, f.y);
        __nv_bfloat162 hi = __floats2bfloat162_rn(f.z, f.w);
        uint2 o; o.x = *reinterpret_cast<uint32_t*>(&lo); o.y = *reinterpret_cast<uint32_t*>(&hi);
        *reinterpret_cast<uint2*>(&wcomb_s[e * EMB_LD + v * 4]) = o;
    }

    __nv_bfloat16* xwg  = g_xw   + (size_t)w * CC * NPAD;
    __nv_bfloat16* embT = g_embT + (size_t)w * NPAD * CC;
    __syncthreads();

    uint32_t aAdr = s2u(&xb_s[(rw * 16 + lA) * EMB_LD + kA]);
    uint32_t bAdr = s2u(&wcomb_s[(cw * 64 + nh * 8 + lB8) * EMB_LD + sel * 8]);
    int eoff = half * 128 + cw * 64;

    for (int blk = 0; blk < NBLK_E; blk++) {
        // gather this block's window slice into xb_s (co-resident CTA hides latency)
        #pragma unroll
        for (int it = 0; it < 64; it++) {
            int idx = tid + it * NTH_E;
            int nn = idx % EBR, c = idx / EBR;
            int m = blk * EBR + nn;
            float v = (m < NTOK) ? xb[((size_t)c * HH + h0 + m / WSZ) * HH + w0 + m % WSZ] : 0.f;
            __nv_bfloat16 bv = __float2bfloat16(v);
            xb_s[nn * EMB_LD + c] = bv;
            if (half == 0) xwg[c * NPAD + m] = bv;
        }
        __syncthreads();

        // GEMM: [48][128] = xb @ wcomb_half^T, k=256
        float acc[8][4];
        #pragma unroll
        for (int t = 0; t < 8; t++) { acc[t][0]=0.f; acc[t][1]=0.f; acc[t][2]=0.f; acc[t][3]=0.f; }
        #pragma unroll
        for (int kt = 0; kt < 16; kt++) {
            uint32_t a0, a1, a2, a3;
            ldsm4(a0, a1, a2, a3, aAdr + kt * 32);
            #pragma unroll
            for (int p = 0; p < 4; p++) {
                uint32_t b0, b1, b2, b3;
                ldsm4(b0, b1, b2, b3, bAdr + (p * 16 * EMB_LD + kt * 16) * 2);
                mma16816(acc[2*p],   a0, a1, a2, a3, b0, b1);
                mma16816(acc[2*p+1], a0, a1, a2, a3, b2, b3);
            }
        }
        {
            int r0 = blk * EBR + rw * 16 + g, r1 = r0 + 8;
            #pragma unroll
            for (int t = 0; t < 8; t++) {
                int e0 = eoff + t * 8 + q * 2;
                st_bf2(&embT[r0 * CC + e0], acc[t][0], acc[t][1]);
                st_bf2(&embT[r1 * CC + e0], acc[t][2], acc[t][3]);
            }
        }
        __syncthreads();
    }
}

// ---------------- kernel 2: attn v4 (byte-identical R16) ----------------
__global__ __launch_bounds__(NTH_A, 2) void attn_kernel(const float* __restrict__ x,
                                                        float* __restrict__ out) {
    extern __shared__ char smem_raw[];
    __nv_bfloat16* sm    = reinterpret_cast<__nv_bfloat16*>(smem_raw);
    __nv_bfloat16* th_s  = sm;                       // [48][TH_LD]
    __nv_bfloat16* P_s   = sm + OFF_P;               // [48][P_LD]
    __nv_bfloat16* zb[2] = { sm + OFF_ZONE, sm + OFF_ZONE + ZONE_HALF };
    float* stats_max = reinterpret_cast<float*>(sm + OFF_END);
    float* stats_sum = stats_max + BLKR2 * 2;
    float* out_s = reinterpret_cast<float*>(zb[1]);  // fp32 [48][129] (always zone1)

    int bid = blockIdx.x;
    int w = bid / NBLK_E, blk = bid - w * NBLK_E;
    int b = w / 100, rem = w % 100, wh = rem / 10, ww = rem % 10;
    int h0 = wh * WSZ, w0 = ww * WSZ;
    int tid = threadIdx.x;
    int warp = tid >> 5, lane = tid & 31;
    int rw = warp >> 1, cw = warp & 1;   // 3 x 2
    int g = lane >> 2, q = lane & 3;
    int lA = lane & 15, kA = (lane >> 4) << 3;
    int lB8 = lane & 7, sel = (lane >> 3) & 1, nh = lane >> 4;

    const __nv_bfloat16* embT = g_embT + (size_t)w * NPAD * CC;
    const __nv_bfloat16* xwg  = g_xw   + (size_t)w * CC * NPAD;

    const float scale = 0.08838834764831845f;  // 1/sqrt(128)

    uint32_t aTh = s2u(&th_s[(rw * 16 + lA) * TH_LD + kA]);
    uint32_t aP  = s2u(&P_s[(rw * 16 + lA) * P_LD + kA]);
    uint32_t bPhiP[2] = { s2u(&zb[0][(cw * 56 + nh * 8 + lB8) * TH_LD + sel * 8]),
                          s2u(&zb[1][(cw * 56 + nh * 8 + lB8) * TH_LD + sel * 8]) };
    uint32_t bPhiS[2] = { s2u(&zb[0][(cw * 56 + 48 + lB8) * TH_LD + sel * 8]),
                          s2u(&zb[1][(cw * 56 + 48 + lB8) * TH_LD + sel * 8]) };
    uint32_t bAvP[2] = { s2u(&zb[0][(cw * 128 + nh * 8 + lB8) * AV_LD + sel * 8]),
                         s2u(&zb[1][(cw * 128 + nh * 8 + lB8) * AV_LD + sel * 8]) };
    uint32_t bPjP[2] = { s2u(&zb[0][(nh * 8 + lB8) * PJ_LD + cw * 32 + sel * 8]),
                         s2u(&zb[1][(nh * 8 + lB8) * PJ_LD + cw * 32 + sel * 8]) };

    int v6 = tid % 6, c6 = tid / 6;
    int nl = tid % 48, ob = tid / 48;

    int ng = blk * BLKR2 + nl;
    bool evalid = (ng < NTOK);
    size_t ebase = 0;
    if (evalid) {
        int i = ng / WSZ, j = ng - i * WSZ;
        ebase = ((size_t)b * CC * HH + h0 + i) * HH + w0 + j;
    }

    // ---- S phase ----
    for (int idx = tid; idx < SCH * 16; idx += NTH_A) {
        int mm = idx >> 4, v = idx & 15;
        cpasync16(&zb[0][mm * TH_LD + v * 8], &embT[mm * CC + CE + v * 8]);
    }
    CP_COMMIT();
    for (int idx = tid; idx < BLKR2 * 16; idx += NTH_A) {
        int r = idx >> 4, v = idx & 15;
        cp16(&th_s[r * TH_LD + v * 8], &embT[(blk * BLKR2 + r) * CC + v * 8]);
    }

    float sacc[21][4];
    #pragma unroll
    for (int t = 0; t < 21; t++) { sacc[t][0]=0.f; sacc[t][1]=0.f; sacc[t][2]=0.f; sacc[t][3]=0.f; }
    for (int mc = 0; mc < 3; mc++) {
        if (mc < 2) {
            for (int idx = tid; idx < SCH * 16; idx += NTH_A) {
                int mm = idx >> 4, v = idx & 15;
                cpasync16(&zb[(mc + 1) & 1][mm * TH_LD + v * 8],
                          &embT[((mc + 1) * SCH + mm) * CC + CE + v * 8]);
            }
            CP_COMMIT();
            CP_WAIT1();
        } else {
            CP_WAIT0();
        }
        __syncthreads();
        uint32_t bP = bPhiP[mc & 1], bS = bPhiS[mc & 1];
        #pragma unroll
        for (int kt = 0; kt < 8; kt++) {
            uint32_t a0, a1, a2, a3;
            ldsm4(a0, a1, a2, a3, aTh + kt * 32);
            #pragma unroll
            for (int p = 0; p < 3; p++) {
                uint32_t b0, b1, b2, b3;
                ldsm4(b0, b1, b2, b3, bP + (p * 16 * TH_LD + kt * 16) * 2);
                mma16816(sacc[mc * 7 + 2*p],   a0, a1, a2, a3, b0, b1);
                mma16816(sacc[mc * 7 + 2*p+1], a0, a1, a2, a3, b2, b3);
            }
            {
                uint32_t b0, b1;
                ldsm2(b0, b1, bS + kt * 32);
                mma16816(sacc[mc * 7 + 6], a0, a1, a2, a3, b0, b1);
            }
        }
        __syncthreads();
    }
    // prefetch AV chunk 0 -> zb1
    {
        const __nv_bfloat16* src = xwg + c6 * NPAD + v6 * 8;
        __nv_bfloat16* dst = zb[1] + c6 * AV_LD + v6 * 8;
        #pragma unroll
        for (int it = 0; it < 8; it++)
            cpasync16(dst + it * 32 * AV_LD, src + it * 32 * NPAD);
    }
    CP_COMMIT();

    // ---- softmax ----
    #pragma unroll
    for (int mc = 0; mc < 3; mc++) {
        #pragma unroll
        for (int t = 0; t < 7; t++) {
            int c0 = mc * SCH + cw * 56 + t * 8 + q * 2;
            float* sv = sacc[mc * 7 + t];
            #pragma unroll
            for (int i = 0; i < 4; i++) {
                float v = sv[i] * scale;
                int col = c0 + (i & 1);
                if (col >= NTOK) v = -1e30f;
                sv[i] = v;
            }
        }
    }
    float m0 = -1e30f, m1 = -1e30f;
    #pragma unroll
    for (int t = 0; t < 21; t++) {
        m0 = fmaxf(m0, fmaxf(sacc[t][0], sacc[t][1]));
        m1 = fmaxf(m1, fmaxf(sacc[t][2], sacc[t][3]));
    }
    m0 = fmaxf(m0, __shfl_xor_sync(0xffffffffu, m0, 1));
    m0 = fmaxf(m0, __shfl_xor_sync(0xffffffffu, m0, 2));
    m1 = fmaxf(m1, __shfl_xor_sync(0xffffffffu, m1, 1));
    m1 = fmaxf(m1, __shfl_xor_sync(0xffffffffu, m1, 2));
    int row0 = rw * 16 + g, row1 = row0 + 8;
    if (q == 0) { stats_max[row0 * 2 + cw] = m0; stats_max[row1 * 2 + cw] = m1; }
    __syncthreads();
    float rmax0 = fmaxf(stats_max[row0 * 2], stats_max[row0 * 2 + 1]);
    float rmax1 = fmaxf(stats_max[row1 * 2], stats_max[row1 * 2 + 1]);
    float s0 = 0.f, s1 = 0.f;
    #pragma unroll
    for (int t = 0; t < 21; t++) {
        sacc[t][0] = __expf(sacc[t][0] - rmax0);
        sacc[t][1] = __expf(sacc[t][1] - rmax0);
        sacc[t][2] = __expf(sacc[t][2] - rmax1);
        sacc[t][3] = __expf(sacc[t][3] - rmax1);
        s0 += sacc[t][0] + sacc[t][1];
        s1 += sacc[t][2] + sacc[t][3];
    }
    s0 += __shfl_xor_sync(0xffffffffu, s0, 1);
    s0 += __shfl_xor_sync(0xffffffffu, s0, 2);
    s1 += __shfl_xor_sync(0xffffffffu, s1, 1);
    s1 += __shfl_xor_sync(0xffffffffu, s1, 2);
    if (q == 0) { stats_sum[row0 * 2 + cw] = s0; stats_sum[row1 * 2 + cw] = s1; }
    __syncthreads();
    float inv0 = 1.f / (stats_sum[row0 * 2] + stats_sum[row0 * 2 + 1]);
    float inv1 = 1.f / (stats_sum[row1 * 2] + stats_sum[row1 * 2 + 1]);
    #pragma unroll
    for (int mc = 0; mc < 3; mc++) {
        #pragma unroll
        for (int t = 0; t < 7; t++) {
            int c0 = mc * SCH + cw * 56 + t * 8 + q * 2;
            float* sv = sacc[mc * 7 + t];
            st_bf2(&P_s[row0 * P_LD + c0], sv[0] * inv0, sv[1] * inv0);
            st_bf2(&P_s[row1 * P_LD + c0], sv[2] * inv1, sv[3] * inv1);
        }
    }

    // ---- AV ----
    float yacc[16][4];
    #pragma unroll
    for (int t = 0; t < 16; t++) { yacc[t][0]=0.f; yacc[t][1]=0.f; yacc[t][2]=0.f; yacc[t][3]=0.f; }
    for (int mc = 0; mc < 7; mc++) {
        if (mc < 6) {
            const __nv_bfloat16* src = xwg + c6 * NPAD + (mc + 1) * AVK + v6 * 8;
            __nv_bfloat16* dst = zb[mc & 1] + c6 * AV_LD + v6 * 8;
            #pragma unroll
            for (int it = 0; it < 8; it++)
                cpasync16(dst + it * 32 * AV_LD, src + it * 32 * NPAD);
            CP_COMMIT();
            CP_WAIT1();
        } else {
            CP_WAIT0();
        }
        __syncthreads();
        uint32_t bAv = bAvP[(mc + 1) & 1];
        #pragma unroll
        for (int kt = 0; kt < 3; kt++) {
            uint32_t a0, a1, a2, a3;
            ldsm4(a0, a1, a2, a3, aP + (mc * AVK + kt * 16) * 2);
            #pragma unroll
            for (int p = 0; p < 8; p++) {
                uint32_t b0, b1, b2, b3;
                ldsm4(b0, b1, b2, b3, bAv + (p * 16 * AV_LD + kt * 16) * 2);
                mma16816(yacc[2*p],   a0, a1, a2, a3, b0, b1);
                mma16816(yacc[2*p+1], a0, a1, a2, a3, b2, b3);
            }
        }
        __syncthreads();
    }

    // ---- pack y into proj A-fragments ----
    uint32_t pY[8][4];
    #pragma unroll
    for (int t = 0; t < 8; t++) {
        pY[t][0] = pk2(yacc[2*t][0],   yacc[2*t][1]);
        pY[t][1] = pk2(yacc[2*t][2],   yacc[2*t][3]);
        pY[t][2] = pk2(yacc[2*t+1][0], yacc[2*t+1][1]);
        pY[t][3] = pk2(yacc[2*t+1][2], yacc[2*t+1][3]);
    }

    // ---- proj (k split by cw, merged in epilogue) ----
    for (int idx = tid; idx < 128 * 8; idx += NTH_A) {
        int o = idx >> 3, u = idx & 7;
        int csrc = (u < 4) ? (u * 8) : (128 + (u - 4) * 8);
        cpasync16(&zb[0][o * PJ_LD + u * 8], &g_wprojb[o * CC + csrc]);
    }
    CP_COMMIT();

    float pacc[16][4];
    #pragma unroll
    for (int t = 0; t < 16; t++) { pacc[t][0]=0.f; pacc[t][1]=0.f; pacc[t][2]=0.f; pacc[t][3]=0.f; }

    for (int h = 0; h < 2; h++) {
        for (int sp = 0; sp < 4; sp++) {
            int sidx = h * 4 + sp;
            if (sidx < 7) {
                int nidx = sidx + 1, nh2 = nidx >> 2, nsp = nidx & 3;
                for (int idx = tid; idx < 128 * 8; idx += NTH_A) {
                    int o = idx >> 3, u = idx & 7;
                    int csrc = (u < 4) ? (nsp * 32 + u * 8) : (128 + nsp * 32 + (u - 4) * 8);
                    cpasync16(&zb[nidx & 1][o * PJ_LD + u * 8],
                              &g_wprojb[(nh2 * 128 + o) * CC + csrc]);
                }
                CP_COMMIT();
                CP_WAIT1();
            } else {
                CP_WAIT0();
            }
            __syncthreads();
            uint32_t bPj = bPjP[sidx & 1];
            #pragma unroll
            for (int kt = 0; kt < 2; kt++) {
                int s = sp * 2 + kt;
                uint32_t a0 = pY[s][0], a1 = pY[s][1], a2 = pY[s][2], a3 = pY[s][3];
                #pragma unroll
                for (int p = 0; p < 8; p++) {
                    uint32_t b0, b1, b2, b3;
                    ldsm4(b0, b1, b2, b3, bPj + (p * 16 * PJ_LD + kt * 16) * 2);
                    mma16816(pacc[2*p],   a0, a1, a2, a3, b0, b1);
                    mma16816(pacc[2*p+1], a0, a1, a2, a3, b2, b3);
                }
            }
            __syncthreads();
        }

        // ---- epilogue for o-half h ----
        int r0 = rw * 16 + g, r1 = r0 + 8;
        if (cw == 0) {
            #pragma unroll
            for (int tl = 0; tl < 16; tl++) {
                int cc = tl * 8 + q * 2;
                out_s[r0 * 129 + cc]     = pacc[tl][0];
                out_s[r0 * 129 + cc + 1] = pacc[tl][1];
                out_s[r1 * 129 + cc]     = pacc[tl][2];
                out_s[r1 * 129 + cc + 1] = pacc[tl][3];
            }
        }
        __syncthreads();
        if (cw == 1) {
            #pragma unroll
            for (int tl = 0; tl < 16; tl++) {
                int cc = tl * 8 + q * 2;
                out_s[r0 * 129 + cc]     += pacc[tl][0];
                out_s[r0 * 129 + cc + 1] += pacc[tl][1];
                out_s[r1 * 129 + cc]     += pacc[tl][2];
                out_s[r1 * 129 + cc + 1] += pacc[tl][3];
            }
        }
        __syncthreads();
        if (evalid) {
            const float* os = out_s + nl * 129;
            #pragma unroll
            for (int it = 0; it < 32; it++) {
                int ol = ob + it * 4;
                size_t gi = ebase + (size_t)(h * 128 + ol) * (HH * HH);
                out[gi] = x[gi] + os[ol];
            }
        }
        __syncthreads();
        if (h == 0) {
            #pragma unroll
            for (int t = 0; t < 16; t++) { pacc[t][0]=0.f; pacc[t][1]=0.f; pacc[t][2]=0.f; pacc[t][3]=0.f; }
        }
    }
}

// ---------------- launch ----------------
extern "C" void kernel_launch(void* const* d_in, const int* in_sizes, int n_in,
                              void* d_out, int out_size) {
    const float* x     = (const float*)d_in[0];
    const float* wt    = (const float*)d_in[1];
    const float* wp    = (const float*)d_in[2];
    const float* wproj = (const float*)d_in[3];
    float* out = (float*)d_out;

    cudaFuncSetAttribute(embed_kernel, cudaFuncAttributeMaxDynamicSharedMemorySize, EMBED_SMEM);
    cudaFuncSetAttribute(attn_kernel,  cudaFuncAttributeMaxDynamicSharedMemorySize, ATTN_SMEM);

    embed_kernel<<<NWIN * 2, NTH_E, EMBED_SMEM>>>(x, wt, wp, wproj);
    attn_kernel<<<NWIN * NBLK_E, NTH_A, ATTN_SMEM>>>(x, out);
}